// round 1
// baseline (speedup 1.0000x reference)
#include <cuda_runtime.h>
#include <cuda_bf16.h>

#define V_DIM 32
#define NB 14          // N_BASIS
#define NP 496         // V*(V-1)/2
#define RPB 8          // rows per block (one per warp)
#define NTHREADS 256

struct SmemLayout {
    float P[NB * NP];                 // params staged once per block (27776 B)
    float xs[RPB][V_DIM];             // raw input row
    float Bs[RPB][31][4];             // 4 nonzero cubic basis values per column
    int   Js[RPB][31];                // basis base row j0 per column
    float Ls[RPB][NP];                // lam values
    unsigned char ctab[NP];           // pair index -> column c
};

__global__ void decor_kernel(const float* __restrict__ input,
                             const float* __restrict__ params,
                             float* __restrict__ d_out,
                             int n)
{
    extern __shared__ char smem_raw[];
    SmemLayout* S = reinterpret_cast<SmemLayout*>(smem_raw);

    const int tid = threadIdx.x;

    // Stage params into smem (reused by all 8 rows in this block)
    for (int i = tid; i < NB * NP; i += NTHREADS) S->P[i] = params[i];
    // Build pair->column table: pairs ordered as np.tril_indices (v=1..31, c=0..v-1)
    if (tid >= 1 && tid < V_DIM) {
        int v = tid;
        int base = v * (v - 1) / 2;
        for (int c = 0; c < v; c++) S->ctab[base + c] = (unsigned char)c;
    }
    __syncthreads();

    const int warp = tid >> 5;
    const int lane = tid & 31;
    const int row  = blockIdx.x * RPB + warp;
    if (row >= n) return;   // whole warp exits together; no block syncs after this

    const float LOv = -15.0f, HIv = 15.0f;
    const float inv_dist = 11.0f / (HIv - LOv);

    // Load input row (coalesced 128B)
    float xi = input[(size_t)row * V_DIM + lane];
    S->xs[warp][lane] = xi;

    // Cubic uniform B-spline: only 4 basis funcs nonzero at x, closed form
    if (lane < 31) {
        float xc = fminf(fmaxf(xi, LOv), HIv - 1e-6f);
        float s  = (xc - LOv) * inv_dist;       // in [0, 11)
        int j0 = (int)floorf(s);
        j0 = min(max(j0, 0), 10);
        float u  = s - (float)j0;
        float um = 1.0f - u;
        float u2 = u * u, u3 = u2 * u;
        S->Bs[warp][lane][0] = um * um * um * (1.0f / 6.0f);
        S->Bs[warp][lane][1] = (3.0f * u3 - 6.0f * u2 + 4.0f) * (1.0f / 6.0f);
        S->Bs[warp][lane][2] = (-3.0f * u3 + 3.0f * u2 + 3.0f * u + 1.0f) * (1.0f / 6.0f);
        S->Bs[warp][lane][3] = u3 * (1.0f / 6.0f);
        S->Js[warp][lane] = j0;
    }
    __syncwarp();

    // lam[p] = sum of 4 basis values * params rows j0..j0+3, column p
    #pragma unroll
    for (int i = 0; i < 16; i++) {
        int p = lane + i * 32;
        if (p < NP) {
            int c  = S->ctab[p];
            int j0 = S->Js[warp][c];
            float b0 = S->Bs[warp][c][0];
            float b1 = S->Bs[warp][c][1];
            float b2 = S->Bs[warp][c][2];
            float b3 = S->Bs[warp][c][3];
            const float* Pp = S->P + p;
            float l = b0 * Pp[(size_t)j0 * NP];
            l = fmaf(b1, Pp[(size_t)(j0 + 1) * NP], l);
            l = fmaf(b2, Pp[(size_t)(j0 + 2) * NP], l);
            l = fmaf(b3, Pp[(size_t)(j0 + 3) * NP], l);
            S->Ls[warp][p] = l;
        }
    }
    __syncwarp();

    // Write lm row: 1024 floats = 256 float4, lane-consecutive (coalesced STG.128)
    float* lm = d_out + (size_t)n * V_DIM;                       // lm block starts after 'out'
    float4* lmrow = reinterpret_cast<float4*>(lm + (size_t)row * V_DIM * V_DIM);
    #pragma unroll
    for (int i = 0; i < 8; i++) {
        int t4 = lane + i * 32;          // 0..255
        int v  = t4 >> 3;                // element / 32
        int c0 = (t4 & 7) << 2;          // starting column (multiple of 4, same v for all 4)
        int pb = v * (v - 1) / 2;
        float vals[4];
        #pragma unroll
        for (int q = 0; q < 4; q++) {
            int c = c0 + q;
            float val = 0.0f;
            if (c < v)      val = S->Ls[warp][pb + c];
            else if (c == v) val = 1.0f;
            vals[q] = val;
        }
        lmrow[t4] = make_float4(vals[0], vals[1], vals[2], vals[3]);
    }

    // out[row, v] = input[row, v] + sum_{c<v} lam[(v,c)] * input[row, c]
    float acc = S->xs[warp][lane];
    int pb = lane * (lane - 1) / 2;
    for (int c = 0; c < lane; c++)
        acc = fmaf(S->Ls[warp][pb + c], S->xs[warp][c], acc);
    d_out[(size_t)row * V_DIM + lane] = acc;
}

// Penalties: second_pen, first_pen, param_pen over the tiny (14,496) params
__global__ void pen_kernel(const float* __restrict__ params, float* __restrict__ scal)
{
    __shared__ float red[3][8];
    float s0 = 0.f, s1 = 0.f, s2 = 0.f;   // param_pen, first_pen, second_pen
    for (int i = threadIdx.x; i < NB * NP; i += 256) {
        float p0 = params[i];
        s0 += p0 * p0;
        int k = i / NP;
        if (k < NB - 1) {
            float p1 = params[i + NP];
            float a = p1 - p0;
            s1 += a * a;
            if (k < NB - 2) {
                float b = params[i + 2 * NP] - 2.0f * p1 + p0;
                s2 += b * b;
            }
        }
    }
    #pragma unroll
    for (int off = 16; off > 0; off >>= 1) {
        s0 += __shfl_down_sync(0xffffffffu, s0, off);
        s1 += __shfl_down_sync(0xffffffffu, s1, off);
        s2 += __shfl_down_sync(0xffffffffu, s2, off);
    }
    int warp = threadIdx.x >> 5, lane = threadIdx.x & 31;
    if (lane == 0) { red[0][warp] = s2; red[1][warp] = s1; red[2][warp] = s0; }
    __syncthreads();
    if (threadIdx.x < 3) {
        float t = 0.f;
        #pragma unroll
        for (int w = 0; w < 8; w++) t += red[threadIdx.x][w];
        scal[threadIdx.x] = t;   // [0]=second_pen, [1]=first_pen, [2]=param_pen
    }
}

extern "C" void kernel_launch(void* const* d_in, const int* in_sizes, int n_in,
                              void* d_out, int out_size)
{
    const float* input  = (const float*)d_in[0];
    // d_in[1] = log_d (unused by the reference's outputs)
    const float* params = (const float*)d_in[2];
    float* outp = (float*)d_out;
    int n = in_sizes[0] / V_DIM;

    size_t smem = sizeof(SmemLayout);
    cudaFuncSetAttribute(decor_kernel, cudaFuncAttributeMaxDynamicSharedMemorySize, (int)smem);

    int blocks = (n + RPB - 1) / RPB;
    decor_kernel<<<blocks, NTHREADS, smem>>>(input, params, outp, n);

    // scalars live after out (n*32) and lm (n*1024)
    float* scal = outp + (size_t)n * V_DIM + (size_t)n * V_DIM * V_DIM;
    pen_kernel<<<1, 256>>>(params, scal);
}

// round 2
// speedup vs baseline: 1.3282x; 1.3282x over previous
#include <cuda_runtime.h>
#include <cuda_bf16.h>

#define V_DIM 32
#define NB 14          // N_BASIS
#define NP 496         // V*(V-1)/2
#define NW 16          // warps per block (rows processed concurrently)
#define NTHREADS 512
#define GRID 296       // 2 blocks per SM on 148 SMs

struct SmemLayout {
    float P[NB * NP];                 // params staged once per block (27776 B)
    float xs[NW][V_DIM];              // raw input row
    float Bs[NW][31][4];              // 4 nonzero cubic basis values per column
    int   Js[NW][31];                 // basis base row j0 per column
    float Ls[NW][NP];                 // lam values
    float red[3][NW];                 // penalty reduction scratch (block 0)
    unsigned char ctab[NP];           // pair index -> column c
};

__global__ __launch_bounds__(NTHREADS, 2)
void decor_kernel(const float* __restrict__ input,
                  const float* __restrict__ params,
                  float* __restrict__ d_out,
                  float* __restrict__ scal,
                  int n)
{
    extern __shared__ char smem_raw[];
    SmemLayout* S = reinterpret_cast<SmemLayout*>(smem_raw);

    const int tid = threadIdx.x;

    // ---- Stage params into smem once per block ----
    for (int i = tid; i < NB * NP; i += NTHREADS) S->P[i] = params[i];
    // pair->column table: tril_indices order (v=1..31, c=0..v-1)
    if (tid >= 1 && tid < V_DIM) {
        int v = tid;
        int base = v * (v - 1) / 2;
        for (int c = 0; c < v; c++) S->ctab[base + c] = (unsigned char)c;
    }
    __syncthreads();

    // ---- Block 0: fused penalty computation from smem-staged params ----
    if (blockIdx.x == 0) {
        float s0 = 0.f, s1 = 0.f, s2 = 0.f;   // param, first, second
        for (int i = tid; i < NB * NP; i += NTHREADS) {
            float p0 = S->P[i];
            s0 += p0 * p0;
            int k = i / NP;
            if (k < NB - 1) {
                float p1 = S->P[i + NP];
                float a = p1 - p0;
                s1 += a * a;
                if (k < NB - 2) {
                    float b = S->P[i + 2 * NP] - 2.0f * p1 + p0;
                    s2 += b * b;
                }
            }
        }
        #pragma unroll
        for (int off = 16; off > 0; off >>= 1) {
            s0 += __shfl_down_sync(0xffffffffu, s0, off);
            s1 += __shfl_down_sync(0xffffffffu, s1, off);
            s2 += __shfl_down_sync(0xffffffffu, s2, off);
        }
        int w = tid >> 5, l = tid & 31;
        if (l == 0) { S->red[0][w] = s2; S->red[1][w] = s1; S->red[2][w] = s0; }
        __syncthreads();
        if (tid < 3) {
            float t = 0.f;
            #pragma unroll
            for (int w2 = 0; w2 < NW; w2++) t += S->red[tid][w2];
            scal[tid] = t;   // [0]=second_pen, [1]=first_pen, [2]=param_pen
        }
    }

    const int warp = tid >> 5;
    const int lane = tid & 31;

    const float LOv = -15.0f, HIv = 15.0f;
    const float inv_dist = 11.0f / (HIv - LOv);

    float* lm = d_out + (size_t)n * V_DIM;   // lm block starts after 'out'
    const int row_stride = gridDim.x * NW;

    for (int row = blockIdx.x * NW + warp; row < n; row += row_stride) {

        // Load input row (coalesced 128B)
        float xi = input[(size_t)row * V_DIM + lane];
        S->xs[warp][lane] = xi;

        // Cubic uniform B-spline: only 4 basis funcs nonzero, closed form
        if (lane < 31) {
            float xc = fminf(fmaxf(xi, LOv), HIv - 1e-6f);
            float s  = (xc - LOv) * inv_dist;       // in [0, 11)
            int j0 = (int)floorf(s);
            j0 = min(max(j0, 0), 10);
            float u  = s - (float)j0;
            float um = 1.0f - u;
            float u2 = u * u, u3 = u2 * u;
            S->Bs[warp][lane][0] = um * um * um * (1.0f / 6.0f);
            S->Bs[warp][lane][1] = (3.0f * u3 - 6.0f * u2 + 4.0f) * (1.0f / 6.0f);
            S->Bs[warp][lane][2] = (-3.0f * u3 + 3.0f * u2 + 3.0f * u + 1.0f) * (1.0f / 6.0f);
            S->Bs[warp][lane][3] = u3 * (1.0f / 6.0f);
            S->Js[warp][lane] = j0;
        }
        __syncwarp();

        // lam[p] = sum of 4 basis values * params rows j0..j0+3, column p
        #pragma unroll
        for (int i = 0; i < 16; i++) {
            int p = lane + i * 32;
            if (p < NP) {
                int c  = S->ctab[p];
                int j0 = S->Js[warp][c];
                float b0 = S->Bs[warp][c][0];
                float b1 = S->Bs[warp][c][1];
                float b2 = S->Bs[warp][c][2];
                float b3 = S->Bs[warp][c][3];
                const float* Pp = S->P + p;
                float l = b0 * Pp[(size_t)j0 * NP];
                l = fmaf(b1, Pp[(size_t)(j0 + 1) * NP], l);
                l = fmaf(b2, Pp[(size_t)(j0 + 2) * NP], l);
                l = fmaf(b3, Pp[(size_t)(j0 + 3) * NP], l);
                S->Ls[warp][p] = l;
            }
        }
        __syncwarp();

        // Write lm row: 1024 floats = 256 float4, lane-consecutive (STG.128)
        float4* lmrow = reinterpret_cast<float4*>(lm + (size_t)row * V_DIM * V_DIM);
        #pragma unroll
        for (int i = 0; i < 8; i++) {
            int t4 = lane + i * 32;          // 0..255
            int v  = t4 >> 3;
            int c0 = (t4 & 7) << 2;
            int pb = v * (v - 1) / 2;
            float vals[4];
            #pragma unroll
            for (int q = 0; q < 4; q++) {
                int c = c0 + q;
                float val = 0.0f;
                if (c < v)       val = S->Ls[warp][pb + c];
                else if (c == v) val = 1.0f;
                vals[q] = val;
            }
            __stcs(&lmrow[t4], make_float4(vals[0], vals[1], vals[2], vals[3]));
        }

        // out[row, v] = input[row, v] + sum_{c<v} lam[(v,c)] * input[row, c]
        float acc = S->xs[warp][lane];
        int pb = lane * (lane - 1) / 2;
        for (int c = 0; c < lane; c++)
            acc = fmaf(S->Ls[warp][pb + c], S->xs[warp][c], acc);
        d_out[(size_t)row * V_DIM + lane] = acc;

        __syncwarp();   // protect per-warp scratch before next iteration
    }
}

extern "C" void kernel_launch(void* const* d_in, const int* in_sizes, int n_in,
                              void* d_out, int out_size)
{
    const float* input  = (const float*)d_in[0];
    // d_in[1] = log_d (unused by the reference's outputs)
    const float* params = (const float*)d_in[2];
    float* outp = (float*)d_out;
    int n = in_sizes[0] / V_DIM;

    // scalars live after out (n*32) and lm (n*1024)
    float* scal = outp + (size_t)n * V_DIM + (size_t)n * V_DIM * V_DIM;

    size_t smem = sizeof(SmemLayout);
    cudaFuncSetAttribute(decor_kernel, cudaFuncAttributeMaxDynamicSharedMemorySize, (int)smem);

    decor_kernel<<<GRID, NTHREADS, smem>>>(input, params, outp, scal, n);
}